// round 9
// baseline (speedup 1.0000x reference)
#include <cuda_runtime.h>
#include <cuda_bf16.h>
#include <math.h>

// Problem constants
#define BATCH  4
#define T_SEQ  2048
#define CDIM   1024
#define NHEAD  16
#define DHEAD  64
#define MROWS  (BATCH * T_SEQ)   // 8192

// Scratch (allocation-free rule: __device__ globals) — all bf16 hi/lo splits
__device__ __nv_bfloat16 g_ahi[(size_t)MROWS * CDIM];
__device__ __nv_bfloat16 g_alo[(size_t)MROWS * CDIM];
__device__ __nv_bfloat16 g_whi[(size_t)4 * CDIM * CDIM];
__device__ __nv_bfloat16 g_wlo[(size_t)4 * CDIM * CDIM];
__device__ __nv_bfloat16 g_qhi[(size_t)MROWS * CDIM];
__device__ __nv_bfloat16 g_qlo[(size_t)MROWS * CDIM];
__device__ __nv_bfloat16 g_khi[(size_t)MROWS * CDIM];
__device__ __nv_bfloat16 g_klo[(size_t)MROWS * CDIM];
__device__ __nv_bfloat16 g_vhi[(size_t)MROWS * CDIM];
__device__ __nv_bfloat16 g_vlo[(size_t)MROWS * CDIM];

// ---------------------------------------------------------------------------
// fp32 -> bf16 hi/lo split
// ---------------------------------------------------------------------------
__global__ void cvt_split_kernel(const float* __restrict__ in,
                                 __nv_bfloat16* __restrict__ hi,
                                 __nv_bfloat16* __restrict__ lo, int n)
{
    for (int i = blockIdx.x * blockDim.x + threadIdx.x; i < n;
         i += gridDim.x * blockDim.x) {
        float a = in[i];
        __nv_bfloat16 h = __float2bfloat16(a);
        hi[i] = h;
        lo[i] = __float2bfloat16(a - __bfloat162float(h));
    }
}

// ---------------------------------------------------------------------------
// MMA / ldmatrix / cp.async primitives
// ---------------------------------------------------------------------------
__device__ __forceinline__ void mma_bf16(float* d, const unsigned* a, const unsigned* b)
{
    asm volatile(
        "mma.sync.aligned.m16n8k16.row.col.f32.bf16.bf16.f32 "
        "{%0,%1,%2,%3}, {%4,%5,%6,%7}, {%8,%9}, {%0,%1,%2,%3};\n"
        : "+f"(d[0]), "+f"(d[1]), "+f"(d[2]), "+f"(d[3])
        : "r"(a[0]), "r"(a[1]), "r"(a[2]), "r"(a[3]), "r"(b[0]), "r"(b[1]));
}

__device__ __forceinline__ void ldsm_x4(unsigned* r, const void* p)
{
    unsigned addr = (unsigned)__cvta_generic_to_shared(p);
    asm volatile("ldmatrix.sync.aligned.m8n8.x4.shared.b16 {%0,%1,%2,%3}, [%4];\n"
                 : "=r"(r[0]), "=r"(r[1]), "=r"(r[2]), "=r"(r[3]) : "r"(addr));
}

__device__ __forceinline__ void ldsm_x4_t(unsigned* r, const void* p)
{
    unsigned addr = (unsigned)__cvta_generic_to_shared(p);
    asm volatile("ldmatrix.sync.aligned.m8n8.x4.trans.shared.b16 {%0,%1,%2,%3}, [%4];\n"
                 : "=r"(r[0]), "=r"(r[1]), "=r"(r[2]), "=r"(r[3]) : "r"(addr));
}

__device__ __forceinline__ void cp16(void* s, const void* g)
{
    unsigned sa = (unsigned)__cvta_generic_to_shared(s);
    asm volatile("cp.async.cg.shared.global [%0], [%1], 16;\n" :: "r"(sa), "l"(g));
}
#define CP_COMMIT() asm volatile("cp.async.commit_group;\n")
#define CP_WAIT(n)  asm volatile("cp.async.wait_group %0;\n" :: "n"(n))

// ---------------------------------------------------------------------------
// bf16 3-pass (hi/lo split) tensor-core NT GEMM, 3-stage cp.async pipeline.
// OUT_SPLIT=0: fp32 C. OUT_SPLIT=1: bf16 hi/lo outputs, accum scaled by oscale.
// Block tile 128x128x32, 8 warps (2m x 4n), warp tile 64x32, mma m16n8k16.
// ---------------------------------------------------------------------------
#define SLD 40
#define GSTG (128 * SLD)          // elems per array per stage
#define GSTAGE_ELEMS (4 * GSTG)   // 4 arrays (Ah,Al,Bh,Bl)
#define NSTAGE 3
#define GEMM_SMEM (NSTAGE * GSTAGE_ELEMS * sizeof(__nv_bfloat16))  // 120 KB

__device__ __forceinline__ void gemm_stage_load(
    __nv_bfloat16* base,
    const __nv_bfloat16* Ahi, const __nv_bfloat16* Alo,
    const __nv_bfloat16* Bhi, const __nv_bfloat16* Blo,
    int row0, int col0, int K, int k0, int tid)
{
#pragma unroll
    for (int t = 0; t < 2; t++) {
        int c   = tid + t * 256;
        int row = c >> 2;
        int ck  = (c & 3) * 8;
        size_t ga = (size_t)(row0 + row) * K + k0 + ck;
        size_t gb = (size_t)(col0 + row) * K + k0 + ck;
        int d = row * SLD + ck;
        cp16(base + 0 * GSTG + d, Ahi + ga);
        cp16(base + 1 * GSTG + d, Alo + ga);
        cp16(base + 2 * GSTG + d, Bhi + gb);
        cp16(base + 3 * GSTG + d, Blo + gb);
    }
}

template<int OUT_SPLIT>
__global__ __launch_bounds__(256, 1)
void gemm_bf16x3_kernel(const __nv_bfloat16* __restrict__ Ahi,
                        const __nv_bfloat16* __restrict__ Alo,
                        const __nv_bfloat16* __restrict__ Bhi,
                        const __nv_bfloat16* __restrict__ Blo,
                        float* __restrict__ C,
                        __nv_bfloat16* __restrict__ Chi,
                        __nv_bfloat16* __restrict__ Clo,
                        float oscale, int M, int N, int K)
{
    extern __shared__ __align__(16) __nv_bfloat16 dsm[];

    const int tid  = threadIdx.x;
    const int wid  = tid >> 5;
    const int lane = tid & 31;
    const int warp_m = wid & 1;
    const int warp_n = wid >> 1;
    const int row0 = blockIdx.y * 128;
    const int col0 = blockIdx.x * 128;
    const int NIT  = K / 32;

    float acc[4][4][4];
#pragma unroll
    for (int mt = 0; mt < 4; mt++)
#pragma unroll
        for (int nt = 0; nt < 4; nt++)
#pragma unroll
            for (int i = 0; i < 4; i++) acc[mt][nt][i] = 0.f;

    const int j   = lane >> 3;
    const int r   = lane & 7;
    const int a_row  = (j & 1) * 8 + r;
    const int a_kadd = (j >> 1) * 8;
    const int b_row  = (j >> 1) * 8 + r;
    const int b_kadd = (j & 1) * 8;

    // Prefetch stages 0 and 1
    gemm_stage_load(dsm + 0 * GSTAGE_ELEMS, Ahi, Alo, Bhi, Blo, row0, col0, K, 0, tid);
    CP_COMMIT();
    gemm_stage_load(dsm + 1 * GSTAGE_ELEMS, Ahi, Alo, Bhi, Blo, row0, col0, K, 32, tid);
    CP_COMMIT();

    int cur = 0, nxt = 2;
    for (int iter = 0; iter < NIT; iter++) {
        CP_WAIT(1);
        __syncthreads();
        if (iter + 2 < NIT)
            gemm_stage_load(dsm + nxt * GSTAGE_ELEMS, Ahi, Alo, Bhi, Blo,
                            row0, col0, K, (iter + 2) * 32, tid);
        CP_COMMIT();

        const __nv_bfloat16* sAh = dsm + cur * GSTAGE_ELEMS + 0 * GSTG;
        const __nv_bfloat16* sAl = dsm + cur * GSTAGE_ELEMS + 1 * GSTG;
        const __nv_bfloat16* sBh = dsm + cur * GSTAGE_ELEMS + 2 * GSTG;
        const __nv_bfloat16* sBl = dsm + cur * GSTAGE_ELEMS + 3 * GSTG;

#pragma unroll
        for (int ks = 0; ks < 2; ks++) {
            const int kk = ks * 16;
            unsigned ah[4][4], al[4][4], bh[4][2], bl[4][2];
#pragma unroll
            for (int mt = 0; mt < 4; mt++) {
                int m = warp_m * 64 + mt * 16 + a_row;
                ldsm_x4(ah[mt], &sAh[m * SLD + kk + a_kadd]);
                ldsm_x4(al[mt], &sAl[m * SLD + kk + a_kadd]);
            }
#pragma unroll
            for (int p = 0; p < 2; p++) {
                int n = warp_n * 32 + p * 16 + b_row;
                unsigned tmp[4];
                ldsm_x4(tmp, &sBh[n * SLD + kk + b_kadd]);
                bh[p*2][0] = tmp[0]; bh[p*2][1] = tmp[1];
                bh[p*2+1][0] = tmp[2]; bh[p*2+1][1] = tmp[3];
                ldsm_x4(tmp, &sBl[n * SLD + kk + b_kadd]);
                bl[p*2][0] = tmp[0]; bl[p*2][1] = tmp[1];
                bl[p*2+1][0] = tmp[2]; bl[p*2+1][1] = tmp[3];
            }
#pragma unroll
            for (int mt = 0; mt < 4; mt++)
#pragma unroll
                for (int nt = 0; nt < 4; nt++) {
                    mma_bf16(acc[mt][nt], ah[mt], bh[nt]);
                    mma_bf16(acc[mt][nt], ah[mt], bl[nt]);
                    mma_bf16(acc[mt][nt], al[mt], bh[nt]);
                }
        }
        cur = (cur + 1) % NSTAGE;
        nxt = (nxt + 1) % NSTAGE;
    }

    const int g  = lane >> 2;
    const int tt = lane & 3;
#pragma unroll
    for (int mt = 0; mt < 4; mt++) {
        int m = row0 + warp_m * 64 + mt * 16 + g;
#pragma unroll
        for (int nt = 0; nt < 4; nt++) {
            int n = col0 + warp_n * 32 + nt * 8 + 2 * tt;
            if (OUT_SPLIT == 0) {
                *(float2*)&C[(size_t)m * N + n] =
                    make_float2(acc[mt][nt][0], acc[mt][nt][1]);
                *(float2*)&C[(size_t)(m + 8) * N + n] =
                    make_float2(acc[mt][nt][2], acc[mt][nt][3]);
            } else {
#pragma unroll
                for (int rh = 0; rh < 2; rh++) {
                    float v0 = acc[mt][nt][rh*2]   * oscale;
                    float v1 = acc[mt][nt][rh*2+1] * oscale;
                    __nv_bfloat162 h2 = __floats2bfloat162_rn(v0, v1);
                    __nv_bfloat162 l2 = __floats2bfloat162_rn(
                        v0 - __bfloat162float(h2.x), v1 - __bfloat162float(h2.y));
                    size_t idx = (size_t)(m + rh*8) * N + n;
                    *(__nv_bfloat162*)&Chi[idx] = h2;
                    *(__nv_bfloat162*)&Clo[idx] = l2;
                }
            }
        }
    }
}

// ---------------------------------------------------------------------------
// Tensor-core causal flash attention (bf16 hi/lo split, fp32 accum),
// 2-stage cp.async pipeline on K/V tiles.
// BQ=128 (8 warps x 16 rows), BKV=64, D=64. Q pre-scaled by 1/8 at GEMM.
// ---------------------------------------------------------------------------
#define AQ  128
#define AKV 64
#define QSZ (AQ * 64)          // per Q array
#define KSZ (AKV * 64)         // per K/V array
#define KVSTAGE_ELEMS (4 * KSZ)
#define ATTN_SMEM ((2 * QSZ + 2 * KVSTAGE_ELEMS) * sizeof(__nv_bfloat16))  // 96 KB

__device__ __forceinline__ void kv_stage_load(
    __nv_bfloat16* base,
    const __nv_bfloat16* khi, const __nv_bfloat16* klo,
    const __nv_bfloat16* vhi, const __nv_bfloat16* vlo,
    size_t kvbase, int tid)
{
#pragma unroll
    for (int t = 0; t < 2; t++) {
        int i  = tid + t * 256;          // 0..511
        int rr = i >> 3, cg = i & 7;
        int sa = rr * 64 + ((cg ^ (rr & 7)) << 3);
        size_t ga = kvbase + (size_t)rr * CDIM + cg * 8;
        cp16(base + 0 * KSZ + sa, khi + ga);
        cp16(base + 1 * KSZ + sa, klo + ga);
        cp16(base + 2 * KSZ + sa, vhi + ga);
        cp16(base + 3 * KSZ + sa, vlo + ga);
    }
}

__global__ __launch_bounds__(256, 1)
void flash_attn_mma(const __nv_bfloat16* __restrict__ qhi, const __nv_bfloat16* __restrict__ qlo,
                    const __nv_bfloat16* __restrict__ khi, const __nv_bfloat16* __restrict__ klo,
                    const __nv_bfloat16* __restrict__ vhi, const __nv_bfloat16* __restrict__ vlo,
                    __nv_bfloat16* __restrict__ yhi, __nv_bfloat16* __restrict__ ylo)
{
    extern __shared__ __align__(16) __nv_bfloat16 asm_smem[];
    __nv_bfloat16* sQh = asm_smem;
    __nv_bfloat16* sQl = sQh + QSZ;
    __nv_bfloat16* kv0 = sQl + QSZ;     // stage bases: kv0 + s*KVSTAGE_ELEMS

    const int tid  = threadIdx.x;
    const int wid  = tid >> 5;
    const int lane = tid & 31;
    const int g    = lane >> 2;
    const int tt   = lane & 3;
    const int mat  = lane >> 3;
    const int mr   = lane & 7;
    const int bh = blockIdx.y;
    const int b  = bh >> 4;
    const int h  = bh & 15;
    const int q0 = blockIdx.x * AQ;

    const size_t bhbase = ((size_t)(b * T_SEQ)) * CDIM + h * DHEAD;

    // Prefetch KV tile 0 (async), then stage Q (sync loads)
    kv_stage_load(kv0, khi, klo, vhi, vlo, bhbase, tid);
    CP_COMMIT();

    const size_t qbase = bhbase + (size_t)q0 * CDIM;
    for (int i = tid; i < AQ * 8; i += 256) {
        int rr = i >> 3, cg = i & 7;
        int sa = rr * 64 + ((cg ^ (rr & 7)) << 3);
        size_t ga = qbase + (size_t)rr * CDIM + cg * 8;
        *(uint4*)&sQh[sa] = *(const uint4*)&qhi[ga];
        *(uint4*)&sQl[sa] = *(const uint4*)&qlo[ga];
    }

    float o[8][4];
#pragma unroll
    for (int dt = 0; dt < 8; dt++)
#pragma unroll
        for (int i = 0; i < 4; i++) o[dt][i] = 0.f;
    float m0 = -INFINITY, m1 = -INFINITY;
    float l0 = 0.f, l1 = 0.f;

    const int NJ = (q0 + AQ) / AKV;
    for (int jt = 0; jt < NJ; jt++) {
        CP_WAIT(0);
        __syncthreads();
        if (jt + 1 < NJ)
            kv_stage_load(kv0 + ((jt + 1) & 1) * KVSTAGE_ELEMS,
                          khi, klo, vhi, vlo,
                          bhbase + (size_t)((jt + 1) * AKV) * CDIM, tid);
        CP_COMMIT();

        const __nv_bfloat16* sKh = kv0 + (jt & 1) * KVSTAGE_ELEMS + 0 * KSZ;
        const __nv_bfloat16* sKl = kv0 + (jt & 1) * KVSTAGE_ELEMS + 1 * KSZ;
        const __nv_bfloat16* sVh = kv0 + (jt & 1) * KVSTAGE_ELEMS + 2 * KSZ;
        const __nv_bfloat16* sVl = kv0 + (jt & 1) * KVSTAGE_ELEMS + 3 * KSZ;
        const int j0 = jt * AKV;

        // ---- S = Q K^T (3 split passes) ----
        float s[8][4];
#pragma unroll
        for (int nt = 0; nt < 8; nt++)
#pragma unroll
            for (int i = 0; i < 4; i++) s[nt][i] = 0.f;

#pragma unroll
        for (int kc = 0; kc < 4; kc++) {
            unsigned qa_h[4], qa_l[4];
            {
                int row = wid * 16 + (mat & 1) * 8 + mr;
                int cg  = kc * 2 + (mat >> 1);
                int sa  = row * 64 + ((cg ^ (row & 7)) << 3);
                ldsm_x4(qa_h, &sQh[sa]);
                ldsm_x4(qa_l, &sQl[sa]);
            }
#pragma unroll
            for (int jp = 0; jp < 4; jp++) {
                unsigned kb_h[4], kb_l[4];
                int row = jp * 16 + (mat >> 1) * 8 + mr;
                int cg  = kc * 2 + (mat & 1);
                int sa  = row * 64 + ((cg ^ (row & 7)) << 3);
                ldsm_x4(kb_h, &sKh[sa]);
                ldsm_x4(kb_l, &sKl[sa]);
                mma_bf16(s[jp*2],   qa_h, kb_h);
                mma_bf16(s[jp*2],   qa_h, kb_l);
                mma_bf16(s[jp*2],   qa_l, kb_h);
                mma_bf16(s[jp*2+1], qa_h, kb_h + 2);
                mma_bf16(s[jp*2+1], qa_h, kb_l + 2);
                mma_bf16(s[jp*2+1], qa_l, kb_h + 2);
            }
        }

        // ---- causal mask ----
        if (j0 + AKV - 1 > q0 + wid * 16) {
            int row_g  = q0 + wid * 16 + g;
#pragma unroll
            for (int nt = 0; nt < 8; nt++) {
                int col = j0 + nt * 8 + tt * 2;
                if (col     > row_g)     s[nt][0] = -INFINITY;
                if (col + 1 > row_g)     s[nt][1] = -INFINITY;
                if (col     > row_g + 8) s[nt][2] = -INFINITY;
                if (col + 1 > row_g + 8) s[nt][3] = -INFINITY;
            }
        }

        // ---- online softmax ----
        float mx0 = -INFINITY, mx1 = -INFINITY;
#pragma unroll
        for (int nt = 0; nt < 8; nt++) {
            mx0 = fmaxf(mx0, fmaxf(s[nt][0], s[nt][1]));
            mx1 = fmaxf(mx1, fmaxf(s[nt][2], s[nt][3]));
        }
        mx0 = fmaxf(mx0, __shfl_xor_sync(0xffffffffu, mx0, 1));
        mx0 = fmaxf(mx0, __shfl_xor_sync(0xffffffffu, mx0, 2));
        mx1 = fmaxf(mx1, __shfl_xor_sync(0xffffffffu, mx1, 1));
        mx1 = fmaxf(mx1, __shfl_xor_sync(0xffffffffu, mx1, 2));
        float mn0 = fmaxf(m0, mx0), mn1 = fmaxf(m1, mx1);
        float c0 = __expf(m0 - mn0), c1 = __expf(m1 - mn1);
        m0 = mn0; m1 = mn1;
        l0 *= c0;  l1 *= c1;
#pragma unroll
        for (int dt = 0; dt < 8; dt++) {
            o[dt][0] *= c0; o[dt][1] *= c0;
            o[dt][2] *= c1; o[dt][3] *= c1;
        }

        unsigned pH[2][8], pL[2][8];
#pragma unroll
        for (int nt = 0; nt < 8; nt++) {
            float p00 = __expf(s[nt][0] - m0);
            float p01 = __expf(s[nt][1] - m0);
            float p10 = __expf(s[nt][2] - m1);
            float p11 = __expf(s[nt][3] - m1);
            l0 += p00 + p01;
            l1 += p10 + p11;
            __nv_bfloat162 h0 = __floats2bfloat162_rn(p00, p01);
            __nv_bfloat162 h1 = __floats2bfloat162_rn(p10, p11);
            __nv_bfloat162 e0 = __floats2bfloat162_rn(
                p00 - __bfloat162float(h0.x), p01 - __bfloat162float(h0.y));
            __nv_bfloat162 e1 = __floats2bfloat162_rn(
                p10 - __bfloat162float(h1.x), p11 - __bfloat162float(h1.y));
            pH[0][nt] = *reinterpret_cast<unsigned*>(&h0);
            pH[1][nt] = *reinterpret_cast<unsigned*>(&h1);
            pL[0][nt] = *reinterpret_cast<unsigned*>(&e0);
            pL[1][nt] = *reinterpret_cast<unsigned*>(&e1);
        }

        // ---- O += P V (3 split passes) ----
#pragma unroll
        for (int kc = 0; kc < 4; kc++) {
            unsigned pa_h[4] = {pH[0][2*kc], pH[1][2*kc], pH[0][2*kc+1], pH[1][2*kc+1]};
            unsigned pa_l[4] = {pL[0][2*kc], pL[1][2*kc], pL[0][2*kc+1], pL[1][2*kc+1]};
#pragma unroll
            for (int dtp = 0; dtp < 4; dtp++) {
                unsigned vb_h[4], vb_l[4];
                int row = kc * 16 + (mat & 1) * 8 + mr;
                int cg  = dtp * 2 + (mat >> 1);
                int sa  = row * 64 + ((cg ^ (row & 7)) << 3);
                ldsm_x4_t(vb_h, &sVh[sa]);
                ldsm_x4_t(vb_l, &sVl[sa]);
                mma_bf16(o[dtp*2],   pa_h, vb_h);
                mma_bf16(o[dtp*2],   pa_h, vb_l);
                mma_bf16(o[dtp*2],   pa_l, vb_h);
                mma_bf16(o[dtp*2+1], pa_h, vb_h + 2);
                mma_bf16(o[dtp*2+1], pa_h, vb_l + 2);
                mma_bf16(o[dtp*2+1], pa_l, vb_h + 2);
            }
        }
    }

    // ---- epilogue: normalize, split to bf16 hi/lo ----
    l0 += __shfl_xor_sync(0xffffffffu, l0, 1);
    l0 += __shfl_xor_sync(0xffffffffu, l0, 2);
    l1 += __shfl_xor_sync(0xffffffffu, l1, 1);
    l1 += __shfl_xor_sync(0xffffffffu, l1, 2);
    float inv0 = 1.f / l0, inv1 = 1.f / l1;

    size_t orow0 = ((size_t)(b * T_SEQ + q0 + wid * 16 + g)) * CDIM + h * DHEAD;
    size_t orow1 = orow0 + (size_t)8 * CDIM;
#pragma unroll
    for (int dt = 0; dt < 8; dt++) {
        int col = dt * 8 + tt * 2;
        float v0 = o[dt][0] * inv0, v1 = o[dt][1] * inv0;
        __nv_bfloat162 h2 = __floats2bfloat162_rn(v0, v1);
        __nv_bfloat162 l2 = __floats2bfloat162_rn(
            v0 - __bfloat162float(h2.x), v1 - __bfloat162float(h2.y));
        *(__nv_bfloat162*)&yhi[orow0 + col] = h2;
        *(__nv_bfloat162*)&ylo[orow0 + col] = l2;

        float w0 = o[dt][2] * inv1, w1 = o[dt][3] * inv1;
        __nv_bfloat162 h3 = __floats2bfloat162_rn(w0, w1);
        __nv_bfloat162 l3 = __floats2bfloat162_rn(
            w0 - __bfloat162float(h3.x), w1 - __bfloat162float(h3.y));
        *(__nv_bfloat162*)&yhi[orow1 + col] = h3;
        *(__nv_bfloat162*)&ylo[orow1 + col] = l3;
    }
}

// ---------------------------------------------------------------------------
extern "C" void kernel_launch(void* const* d_in, const int* in_sizes, int n_in,
                              void* d_out, int out_size)
{
    const float* x  = (const float*)d_in[0];
    const float* Wq = (const float*)d_in[1];
    const float* Wk = (const float*)d_in[2];
    const float* Wv = (const float*)d_in[3];
    const float* Wp = (const float*)d_in[4];
    float* out = (float*)d_out;

    __nv_bfloat16 *ahi, *alo, *whi, *wlo;
    __nv_bfloat16 *qhi, *qlo, *khi, *klo, *vhi, *vlo;
    cudaGetSymbolAddress((void**)&ahi, g_ahi);
    cudaGetSymbolAddress((void**)&alo, g_alo);
    cudaGetSymbolAddress((void**)&whi, g_whi);
    cudaGetSymbolAddress((void**)&wlo, g_wlo);
    cudaGetSymbolAddress((void**)&qhi, g_qhi);
    cudaGetSymbolAddress((void**)&qlo, g_qlo);
    cudaGetSymbolAddress((void**)&khi, g_khi);
    cudaGetSymbolAddress((void**)&klo, g_klo);
    cudaGetSymbolAddress((void**)&vhi, g_vhi);
    cudaGetSymbolAddress((void**)&vlo, g_vlo);

    cudaFuncSetAttribute(gemm_bf16x3_kernel<0>, cudaFuncAttributeMaxDynamicSharedMemorySize, (int)GEMM_SMEM);
    cudaFuncSetAttribute(gemm_bf16x3_kernel<1>, cudaFuncAttributeMaxDynamicSharedMemorySize, (int)GEMM_SMEM);
    cudaFuncSetAttribute(flash_attn_mma, cudaFuncAttributeMaxDynamicSharedMemorySize, (int)ATTN_SMEM);

    const size_t WSZ = (size_t)CDIM * CDIM;
    const int NX = MROWS * CDIM;

    cvt_split_kernel<<<1024, 256>>>(x,  ahi, alo, NX);
    cvt_split_kernel<<<512, 256>>>(Wq, whi + 0*WSZ, wlo + 0*WSZ, (int)WSZ);
    cvt_split_kernel<<<512, 256>>>(Wk, whi + 1*WSZ, wlo + 1*WSZ, (int)WSZ);
    cvt_split_kernel<<<512, 256>>>(Wv, whi + 2*WSZ, wlo + 2*WSZ, (int)WSZ);
    cvt_split_kernel<<<512, 256>>>(Wp, whi + 3*WSZ, wlo + 3*WSZ, (int)WSZ);

    dim3 ggrid(CDIM / 128, MROWS / 128);   // (8, 64)
    gemm_bf16x3_kernel<1><<<ggrid, 256, GEMM_SMEM>>>(ahi, alo, whi + 0*WSZ, wlo + 0*WSZ,
                                          nullptr, qhi, qlo, 0.125f, MROWS, CDIM, CDIM);
    gemm_bf16x3_kernel<1><<<ggrid, 256, GEMM_SMEM>>>(ahi, alo, whi + 1*WSZ, wlo + 1*WSZ,
                                          nullptr, khi, klo, 1.0f, MROWS, CDIM, CDIM);
    gemm_bf16x3_kernel<1><<<ggrid, 256, GEMM_SMEM>>>(ahi, alo, whi + 2*WSZ, wlo + 2*WSZ,
                                          nullptr, vhi, vlo, 1.0f, MROWS, CDIM, CDIM);

    dim3 agrid(T_SEQ / AQ, BATCH * NHEAD);  // (16, 64)
    flash_attn_mma<<<agrid, 256, ATTN_SMEM>>>(qhi, qlo, khi, klo, vhi, vlo, ahi, alo);

    gemm_bf16x3_kernel<0><<<ggrid, 256, GEMM_SMEM>>>(ahi, alo, whi + 3*WSZ, wlo + 3*WSZ,
                                          out, nullptr, nullptr, 1.0f, MROWS, CDIM, CDIM);
}

// round 13
// speedup vs baseline: 1.3487x; 1.3487x over previous
#include <cuda_runtime.h>
#include <cuda_bf16.h>
#include <math.h>

// Problem constants
#define BATCH  4
#define T_SEQ  2048
#define CDIM   1024
#define NHEAD  16
#define DHEAD  64
#define MROWS  (BATCH * T_SEQ)   // 8192

// Scratch (allocation-free rule: __device__ globals) — all bf16 hi/lo splits
__device__ __nv_bfloat16 g_ahi[(size_t)MROWS * CDIM];
__device__ __nv_bfloat16 g_alo[(size_t)MROWS * CDIM];
__device__ __nv_bfloat16 g_whi[(size_t)4 * CDIM * CDIM];
__device__ __nv_bfloat16 g_wlo[(size_t)4 * CDIM * CDIM];
__device__ __nv_bfloat16 g_qhi[(size_t)MROWS * CDIM];
__device__ __nv_bfloat16 g_qlo[(size_t)MROWS * CDIM];
__device__ __nv_bfloat16 g_khi[(size_t)MROWS * CDIM];
__device__ __nv_bfloat16 g_klo[(size_t)MROWS * CDIM];
__device__ __nv_bfloat16 g_vhi[(size_t)MROWS * CDIM];
__device__ __nv_bfloat16 g_vlo[(size_t)MROWS * CDIM];

// ---------------------------------------------------------------------------
// fp32 -> bf16 hi/lo split
// ---------------------------------------------------------------------------
__global__ void cvt_split_kernel(const float* __restrict__ in,
                                 __nv_bfloat16* __restrict__ hi,
                                 __nv_bfloat16* __restrict__ lo, int n)
{
    for (int i = blockIdx.x * blockDim.x + threadIdx.x; i < n;
         i += gridDim.x * blockDim.x) {
        float a = in[i];
        __nv_bfloat16 h = __float2bfloat16(a);
        hi[i] = h;
        lo[i] = __float2bfloat16(a - __bfloat162float(h));
    }
}

// ---------------------------------------------------------------------------
// MMA / ldmatrix primitives
// ---------------------------------------------------------------------------
__device__ __forceinline__ void mma_bf16(float* d, const unsigned* a, const unsigned* b)
{
    asm volatile(
        "mma.sync.aligned.m16n8k16.row.col.f32.bf16.bf16.f32 "
        "{%0,%1,%2,%3}, {%4,%5,%6,%7}, {%8,%9}, {%0,%1,%2,%3};\n"
        : "+f"(d[0]), "+f"(d[1]), "+f"(d[2]), "+f"(d[3])
        : "r"(a[0]), "r"(a[1]), "r"(a[2]), "r"(a[3]), "r"(b[0]), "r"(b[1]));
}

__device__ __forceinline__ void ldsm_x4(unsigned* r, const void* p)
{
    unsigned addr = (unsigned)__cvta_generic_to_shared(p);
    asm volatile("ldmatrix.sync.aligned.m8n8.x4.shared.b16 {%0,%1,%2,%3}, [%4];\n"
                 : "=r"(r[0]), "=r"(r[1]), "=r"(r[2]), "=r"(r[3]) : "r"(addr));
}

__device__ __forceinline__ void ldsm_x4_t(unsigned* r, const void* p)
{
    unsigned addr = (unsigned)__cvta_generic_to_shared(p);
    asm volatile("ldmatrix.sync.aligned.m8n8.x4.trans.shared.b16 {%0,%1,%2,%3}, [%4];\n"
                 : "=r"(r[0]), "=r"(r[1]), "=r"(r[2]), "=r"(r[3]) : "r"(addr));
}

// ---------------------------------------------------------------------------
// bf16 3-pass (hi/lo split) tensor-core NT GEMM (sync staging, 2 CTAs/SM).
// OUT_SPLIT=0: fp32 C. OUT_SPLIT=1: bf16 hi/lo outputs, accum scaled by oscale.
// Block tile 128x128x32, 8 warps (2m x 4n), warp tile 64x32, mma m16n8k16.
// ---------------------------------------------------------------------------
#define SLD 40

template<int OUT_SPLIT>
__global__ __launch_bounds__(256, 2)
void gemm_bf16x3_kernel(const __nv_bfloat16* __restrict__ Ahi,
                        const __nv_bfloat16* __restrict__ Alo,
                        const __nv_bfloat16* __restrict__ Bhi,
                        const __nv_bfloat16* __restrict__ Blo,
                        float* __restrict__ C,
                        __nv_bfloat16* __restrict__ Chi,
                        __nv_bfloat16* __restrict__ Clo,
                        float oscale, int M, int N, int K)
{
    __shared__ __align__(16) __nv_bfloat16 sAh[128 * SLD];
    __shared__ __align__(16) __nv_bfloat16 sAl[128 * SLD];
    __shared__ __align__(16) __nv_bfloat16 sBh[128 * SLD];
    __shared__ __align__(16) __nv_bfloat16 sBl[128 * SLD];

    const int tid  = threadIdx.x;
    const int wid  = tid >> 5;
    const int lane = tid & 31;
    const int warp_m = wid & 1;
    const int warp_n = wid >> 1;
    const int row0 = blockIdx.y * 128;
    const int col0 = blockIdx.x * 128;

    float acc[4][4][4];
#pragma unroll
    for (int mt = 0; mt < 4; mt++)
#pragma unroll
        for (int nt = 0; nt < 4; nt++)
#pragma unroll
            for (int i = 0; i < 4; i++) acc[mt][nt][i] = 0.f;

    const int j   = lane >> 3;
    const int r   = lane & 7;
    const int a_row  = (j & 1) * 8 + r;
    const int a_kadd = (j >> 1) * 8;
    const int b_row  = (j >> 1) * 8 + r;
    const int b_kadd = (j & 1) * 8;

    for (int k0 = 0; k0 < K; k0 += 32) {
#pragma unroll
        for (int t = 0; t < 2; t++) {
            int c   = tid + t * 256;
            int row = c >> 2;
            int ck  = (c & 3) * 8;
            size_t ga = (size_t)(row0 + row) * K + k0 + ck;
            size_t gb = (size_t)(col0 + row) * K + k0 + ck;
            int d = row * SLD + ck;
            *(uint4*)&sAh[d] = *(const uint4*)&Ahi[ga];
            *(uint4*)&sAl[d] = *(const uint4*)&Alo[ga];
            *(uint4*)&sBh[d] = *(const uint4*)&Bhi[gb];
            *(uint4*)&sBl[d] = *(const uint4*)&Blo[gb];
        }
        __syncthreads();

#pragma unroll
        for (int ks = 0; ks < 2; ks++) {
            const int kk = ks * 16;
            unsigned ah[4][4], al[4][4], bh[4][2], bl[4][2];
#pragma unroll
            for (int mt = 0; mt < 4; mt++) {
                int m = warp_m * 64 + mt * 16 + a_row;
                ldsm_x4(ah[mt], &sAh[m * SLD + kk + a_kadd]);
                ldsm_x4(al[mt], &sAl[m * SLD + kk + a_kadd]);
            }
#pragma unroll
            for (int p = 0; p < 2; p++) {
                int n = warp_n * 32 + p * 16 + b_row;
                unsigned tmp[4];
                ldsm_x4(tmp, &sBh[n * SLD + kk + b_kadd]);
                bh[p*2][0] = tmp[0]; bh[p*2][1] = tmp[1];
                bh[p*2+1][0] = tmp[2]; bh[p*2+1][1] = tmp[3];
                ldsm_x4(tmp, &sBl[n * SLD + kk + b_kadd]);
                bl[p*2][0] = tmp[0]; bl[p*2][1] = tmp[1];
                bl[p*2+1][0] = tmp[2]; bl[p*2+1][1] = tmp[3];
            }
#pragma unroll
            for (int mt = 0; mt < 4; mt++)
#pragma unroll
                for (int nt = 0; nt < 4; nt++) {
                    mma_bf16(acc[mt][nt], ah[mt], bh[nt]);
                    mma_bf16(acc[mt][nt], ah[mt], bl[nt]);
                    mma_bf16(acc[mt][nt], al[mt], bh[nt]);
                }
        }
        __syncthreads();
    }

    const int g  = lane >> 2;
    const int tt = lane & 3;
#pragma unroll
    for (int mt = 0; mt < 4; mt++) {
        int m = row0 + warp_m * 64 + mt * 16 + g;
#pragma unroll
        for (int nt = 0; nt < 4; nt++) {
            int n = col0 + warp_n * 32 + nt * 8 + 2 * tt;
            if (OUT_SPLIT == 0) {
                *(float2*)&C[(size_t)m * N + n] =
                    make_float2(acc[mt][nt][0], acc[mt][nt][1]);
                *(float2*)&C[(size_t)(m + 8) * N + n] =
                    make_float2(acc[mt][nt][2], acc[mt][nt][3]);
            } else {
#pragma unroll
                for (int rh = 0; rh < 2; rh++) {
                    float v0 = acc[mt][nt][rh*2]   * oscale;
                    float v1 = acc[mt][nt][rh*2+1] * oscale;
                    __nv_bfloat162 h2 = __floats2bfloat162_rn(v0, v1);
                    __nv_bfloat162 l2 = __floats2bfloat162_rn(
                        v0 - __bfloat162float(h2.x), v1 - __bfloat162float(h2.y));
                    size_t idx = (size_t)(m + rh*8) * N + n;
                    *(__nv_bfloat162*)&Chi[idx] = h2;
                    *(__nv_bfloat162*)&Clo[idx] = l2;
                }
            }
        }
    }
}

// ---------------------------------------------------------------------------
// Tensor-core causal flash attention (bf16 hi/lo split, fp32 accum).
// BQ=128 (8 warps x 16 rows), BKV=64, D=64. Q pre-scaled by 1/8 at GEMM.
// S = Qh*Kh + Qh*Kl + Ql*Kh ; PV = Ph*Vh + Ph*Vl + Pl*Vh.
// smem: XOR-swizzled 16B granules (cg ^ (row&7)), rows of 64 bf16.
// ---------------------------------------------------------------------------
#define AQ  128
#define AKV 64

__global__ __launch_bounds__(256, 1)
void flash_attn_mma(const __nv_bfloat16* __restrict__ qhi, const __nv_bfloat16* __restrict__ qlo,
                    const __nv_bfloat16* __restrict__ khi, const __nv_bfloat16* __restrict__ klo,
                    const __nv_bfloat16* __restrict__ vhi, const __nv_bfloat16* __restrict__ vlo,
                    __nv_bfloat16* __restrict__ yhi, __nv_bfloat16* __restrict__ ylo)
{
    extern __shared__ __nv_bfloat16 smem[];
    __nv_bfloat16* sQh = smem;                 // 128*64
    __nv_bfloat16* sQl = sQh + AQ * 64;
    __nv_bfloat16* sKh = sQl + AQ * 64;        // 64*64
    __nv_bfloat16* sKl = sKh + AKV * 64;
    __nv_bfloat16* sVh = sKl + AKV * 64;
    __nv_bfloat16* sVl = sVh + AKV * 64;

    const int tid  = threadIdx.x;
    const int wid  = tid >> 5;
    const int lane = tid & 31;
    const int g    = lane >> 2;
    const int tt   = lane & 3;
    const int mat  = lane >> 3;     // ldmatrix operand index 0..3
    const int mr   = lane & 7;      // row within 8x8 matrix
    const int bh = blockIdx.y;
    const int b  = bh >> 4;
    const int h  = bh & 15;
    const int q0 = blockIdx.x * AQ;

    // Stage Q tile once
    const size_t qbase = ((size_t)(b * T_SEQ + q0)) * CDIM + h * DHEAD;
    for (int i = tid; i < AQ * 8; i += 256) {
        int rr = i >> 3, cg = i & 7;
        int sa = rr * 64 + ((cg ^ (rr & 7)) << 3);
        size_t ga = qbase + (size_t)rr * CDIM + cg * 8;
        *(uint4*)&sQh[sa] = *(const uint4*)&qhi[ga];
        *(uint4*)&sQl[sa] = *(const uint4*)&qlo[ga];
    }
    __syncthreads();

    float o[8][4];
#pragma unroll
    for (int dt = 0; dt < 8; dt++)
#pragma unroll
        for (int i = 0; i < 4; i++) o[dt][i] = 0.f;
    float m0 = -INFINITY, m1 = -INFINITY;
    float l0 = 0.f, l1 = 0.f;

    const int jend = q0 + AQ;
    for (int j0 = 0; j0 < jend; j0 += AKV) {
        // Stage K,V tiles
        const size_t kvbase = ((size_t)(b * T_SEQ + j0)) * CDIM + h * DHEAD;
        for (int i = tid; i < AKV * 8; i += 256) {
            int rr = i >> 3, cg = i & 7;
            int sa = rr * 64 + ((cg ^ (rr & 7)) << 3);
            size_t ga = kvbase + (size_t)rr * CDIM + cg * 8;
            *(uint4*)&sKh[sa] = *(const uint4*)&khi[ga];
            *(uint4*)&sKl[sa] = *(const uint4*)&klo[ga];
            *(uint4*)&sVh[sa] = *(const uint4*)&vhi[ga];
            *(uint4*)&sVl[sa] = *(const uint4*)&vlo[ga];
        }
        __syncthreads();

        // ---- S = Q K^T (3 split passes) ----
        float s[8][4];
#pragma unroll
        for (int nt = 0; nt < 8; nt++)
#pragma unroll
            for (int i = 0; i < 4; i++) s[nt][i] = 0.f;

#pragma unroll
        for (int kc = 0; kc < 4; kc++) {
            unsigned qa_h[4], qa_l[4];
            {
                int row = wid * 16 + (mat & 1) * 8 + mr;
                int cg  = kc * 2 + (mat >> 1);
                int sa  = row * 64 + ((cg ^ (row & 7)) << 3);
                ldsm_x4(qa_h, &sQh[sa]);
                ldsm_x4(qa_l, &sQl[sa]);
            }
#pragma unroll
            for (int jp = 0; jp < 4; jp++) {
                unsigned kb_h[4], kb_l[4];
                int row = jp * 16 + (mat >> 1) * 8 + mr;
                int cg  = kc * 2 + (mat & 1);
                int sa  = row * 64 + ((cg ^ (row & 7)) << 3);
                ldsm_x4(kb_h, &sKh[sa]);
                ldsm_x4(kb_l, &sKl[sa]);
                mma_bf16(s[jp*2],   qa_h, kb_h);
                mma_bf16(s[jp*2],   qa_h, kb_l);
                mma_bf16(s[jp*2],   qa_l, kb_h);
                mma_bf16(s[jp*2+1], qa_h, kb_h + 2);
                mma_bf16(s[jp*2+1], qa_h, kb_l + 2);
                mma_bf16(s[jp*2+1], qa_l, kb_h + 2);
            }
        }

        // ---- causal mask ----
        if (j0 + AKV - 1 > q0 + wid * 16) {
            int row_g  = q0 + wid * 16 + g;
#pragma unroll
            for (int nt = 0; nt < 8; nt++) {
                int col = j0 + nt * 8 + tt * 2;
                if (col     > row_g)     s[nt][0] = -INFINITY;
                if (col + 1 > row_g)     s[nt][1] = -INFINITY;
                if (col     > row_g + 8) s[nt][2] = -INFINITY;
                if (col + 1 > row_g + 8) s[nt][3] = -INFINITY;
            }
        }

        // ---- online softmax ----
        float mx0 = -INFINITY, mx1 = -INFINITY;
#pragma unroll
        for (int nt = 0; nt < 8; nt++) {
            mx0 = fmaxf(mx0, fmaxf(s[nt][0], s[nt][1]));
            mx1 = fmaxf(mx1, fmaxf(s[nt][2], s[nt][3]));
        }
        mx0 = fmaxf(mx0, __shfl_xor_sync(0xffffffffu, mx0, 1));
        mx0 = fmaxf(mx0, __shfl_xor_sync(0xffffffffu, mx0, 2));
        mx1 = fmaxf(mx1, __shfl_xor_sync(0xffffffffu, mx1, 1));
        mx1 = fmaxf(mx1, __shfl_xor_sync(0xffffffffu, mx1, 2));
        float mn0 = fmaxf(m0, mx0), mn1 = fmaxf(m1, mx1);
        float c0 = __expf(m0 - mn0), c1 = __expf(m1 - mn1);
        m0 = mn0; m1 = mn1;
        l0 *= c0;  l1 *= c1;
#pragma unroll
        for (int dt = 0; dt < 8; dt++) {
            o[dt][0] *= c0; o[dt][1] *= c0;
            o[dt][2] *= c1; o[dt][3] *= c1;
        }

        unsigned pH[2][8], pL[2][8];
#pragma unroll
        for (int nt = 0; nt < 8; nt++) {
            float p00 = __expf(s[nt][0] - m0);
            float p01 = __expf(s[nt][1] - m0);
            float p10 = __expf(s[nt][2] - m1);
            float p11 = __expf(s[nt][3] - m1);
            l0 += p00 + p01;
            l1 += p10 + p11;
            __nv_bfloat162 h0 = __floats2bfloat162_rn(p00, p01);
            __nv_bfloat162 h1 = __floats2bfloat162_rn(p10, p11);
            __nv_bfloat162 e0 = __floats2bfloat162_rn(
                p00 - __bfloat162float(h0.x), p01 - __bfloat162float(h0.y));
            __nv_bfloat162 e1 = __floats2bfloat162_rn(
                p10 - __bfloat162float(h1.x), p11 - __bfloat162float(h1.y));
            pH[0][nt] = *reinterpret_cast<unsigned*>(&h0);
            pH[1][nt] = *reinterpret_cast<unsigned*>(&h1);
            pL[0][nt] = *reinterpret_cast<unsigned*>(&e0);
            pL[1][nt] = *reinterpret_cast<unsigned*>(&e1);
        }

        // ---- O += P V (3 split passes) ----
#pragma unroll
        for (int kc = 0; kc < 4; kc++) {
            unsigned pa_h[4] = {pH[0][2*kc], pH[1][2*kc], pH[0][2*kc+1], pH[1][2*kc+1]};
            unsigned pa_l[4] = {pL[0][2*kc], pL[1][2*kc], pL[0][2*kc+1], pL[1][2*kc+1]};
#pragma unroll
            for (int dtp = 0; dtp < 4; dtp++) {
                unsigned vb_h[4], vb_l[4];
                int row = kc * 16 + (mat & 1) * 8 + mr;
                int cg  = dtp * 2 + (mat >> 1);
                int sa  = row * 64 + ((cg ^ (row & 7)) << 3);
                ldsm_x4_t(vb_h, &sVh[sa]);
                ldsm_x4_t(vb_l, &sVl[sa]);
                mma_bf16(o[dtp*2],   pa_h, vb_h);
                mma_bf16(o[dtp*2],   pa_h, vb_l);
                mma_bf16(o[dtp*2],   pa_l, vb_h);
                mma_bf16(o[dtp*2+1], pa_h, vb_h + 2);
                mma_bf16(o[dtp*2+1], pa_h, vb_l + 2);
                mma_bf16(o[dtp*2+1], pa_l, vb_h + 2);
            }
        }
        __syncthreads();
    }

    // ---- epilogue: normalize, split to bf16 hi/lo ----
    l0 += __shfl_xor_sync(0xffffffffu, l0, 1);
    l0 += __shfl_xor_sync(0xffffffffu, l0, 2);
    l1 += __shfl_xor_sync(0xffffffffu, l1, 1);
    l1 += __shfl_xor_sync(0xffffffffu, l1, 2);
    float inv0 = 1.f / l0, inv1 = 1.f / l1;

    size_t orow0 = ((size_t)(b * T_SEQ + q0 + wid * 16 + g)) * CDIM + h * DHEAD;
    size_t orow1 = orow0 + (size_t)8 * CDIM;
#pragma unroll
    for (int dt = 0; dt < 8; dt++) {
        int col = dt * 8 + tt * 2;
        float v0 = o[dt][0] * inv0, v1 = o[dt][1] * inv0;
        __nv_bfloat162 h2 = __floats2bfloat162_rn(v0, v1);
        __nv_bfloat162 l2 = __floats2bfloat162_rn(
            v0 - __bfloat162float(h2.x), v1 - __bfloat162float(h2.y));
        *(__nv_bfloat162*)&yhi[orow0 + col] = h2;
        *(__nv_bfloat162*)&ylo[orow0 + col] = l2;

        float w0 = o[dt][2] * inv1, w1 = o[dt][3] * inv1;
        __nv_bfloat162 h3 = __floats2bfloat162_rn(w0, w1);
        __nv_bfloat162 l3 = __floats2bfloat162_rn(
            w0 - __bfloat162float(h3.x), w1 - __bfloat162float(h3.y));
        *(__nv_bfloat162*)&yhi[orow1 + col] = h3;
        *(__nv_bfloat162*)&ylo[orow1 + col] = l3;
    }
}

// ---------------------------------------------------------------------------
extern "C" void kernel_launch(void* const* d_in, const int* in_sizes, int n_in,
                              void* d_out, int out_size)
{
    const float* x  = (const float*)d_in[0];
    const float* Wq = (const float*)d_in[1];
    const float* Wk = (const float*)d_in[2];
    const float* Wv = (const float*)d_in[3];
    const float* Wp = (const float*)d_in[4];
    float* out = (float*)d_out;

    __nv_bfloat16 *ahi, *alo, *whi, *wlo;
    __nv_bfloat16 *qhi, *qlo, *khi, *klo, *vhi, *vlo;
    cudaGetSymbolAddress((void**)&ahi, g_ahi);
    cudaGetSymbolAddress((void**)&alo, g_alo);
    cudaGetSymbolAddress((void**)&whi, g_whi);
    cudaGetSymbolAddress((void**)&wlo, g_wlo);
    cudaGetSymbolAddress((void**)&qhi, g_qhi);
    cudaGetSymbolAddress((void**)&qlo, g_qlo);
    cudaGetSymbolAddress((void**)&khi, g_khi);
    cudaGetSymbolAddress((void**)&klo, g_klo);
    cudaGetSymbolAddress((void**)&vhi, g_vhi);
    cudaGetSymbolAddress((void**)&vlo, g_vlo);

    static const size_t ATTN_SMEM = (size_t)(AQ * 64 * 2 + AKV * 64 * 4) * sizeof(__nv_bfloat16); // 64KB
    cudaFuncSetAttribute(flash_attn_mma, cudaFuncAttributeMaxDynamicSharedMemorySize, (int)ATTN_SMEM);

    const size_t WSZ = (size_t)CDIM * CDIM;
    const int NX = MROWS * CDIM;

    // Split conversions (input + weights only; y split is fused into attention)
    cvt_split_kernel<<<1024, 256>>>(x,  ahi, alo, NX);
    cvt_split_kernel<<<512, 256>>>(Wq, whi + 0*WSZ, wlo + 0*WSZ, (int)WSZ);
    cvt_split_kernel<<<512, 256>>>(Wk, whi + 1*WSZ, wlo + 1*WSZ, (int)WSZ);
    cvt_split_kernel<<<512, 256>>>(Wv, whi + 2*WSZ, wlo + 2*WSZ, (int)WSZ);
    cvt_split_kernel<<<512, 256>>>(Wp, whi + 3*WSZ, wlo + 3*WSZ, (int)WSZ);

    dim3 ggrid(CDIM / 128, MROWS / 128);   // (8, 64)
    // QKV projections -> bf16 hi/lo (q pre-scaled by 1/sqrt(D) = 0.125)
    gemm_bf16x3_kernel<1><<<ggrid, 256>>>(ahi, alo, whi + 0*WSZ, wlo + 0*WSZ,
                                          nullptr, qhi, qlo, 0.125f, MROWS, CDIM, CDIM);
    gemm_bf16x3_kernel<1><<<ggrid, 256>>>(ahi, alo, whi + 1*WSZ, wlo + 1*WSZ,
                                          nullptr, khi, klo, 1.0f, MROWS, CDIM, CDIM);
    gemm_bf16x3_kernel<1><<<ggrid, 256>>>(ahi, alo, whi + 2*WSZ, wlo + 2*WSZ,
                                          nullptr, vhi, vlo, 1.0f, MROWS, CDIM, CDIM);

    // Attention writes y hi/lo straight into the activation split buffers
    dim3 agrid(T_SEQ / AQ, BATCH * NHEAD);  // (16, 64)
    flash_attn_mma<<<agrid, 256, ATTN_SMEM>>>(qhi, qlo, khi, klo, vhi, vlo, ahi, alo);

    // Output projection -> fp32 out
    gemm_bf16x3_kernel<0><<<ggrid, 256>>>(ahi, alo, whi + 3*WSZ, wlo + 3*WSZ,
                                          out, nullptr, nullptr, 1.0f, MROWS, CDIM, CDIM);
}

// round 17
// speedup vs baseline: 1.4761x; 1.0945x over previous
#include <cuda_runtime.h>
#include <cuda_bf16.h>
#include <math.h>

// Problem constants
#define BATCH  4
#define T_SEQ  2048
#define CDIM   1024
#define NHEAD  16
#define DHEAD  64
#define MROWS  (BATCH * T_SEQ)   // 8192

// Scratch (allocation-free rule: __device__ globals) — all bf16 hi/lo splits
__device__ __nv_bfloat16 g_ahi[(size_t)MROWS * CDIM];
__device__ __nv_bfloat16 g_alo[(size_t)MROWS * CDIM];
__device__ __nv_bfloat16 g_whi[(size_t)4 * CDIM * CDIM];
__device__ __nv_bfloat16 g_wlo[(size_t)4 * CDIM * CDIM];
__device__ __nv_bfloat16 g_qhi[(size_t)MROWS * CDIM];
__device__ __nv_bfloat16 g_qlo[(size_t)MROWS * CDIM];
__device__ __nv_bfloat16 g_khi[(size_t)MROWS * CDIM];
__device__ __nv_bfloat16 g_klo[(size_t)MROWS * CDIM];
__device__ __nv_bfloat16 g_vhi[(size_t)MROWS * CDIM];
__device__ __nv_bfloat16 g_vlo[(size_t)MROWS * CDIM];

// ---------------------------------------------------------------------------
// fp32 -> bf16 hi/lo split
// ---------------------------------------------------------------------------
__global__ void cvt_split_kernel(const float* __restrict__ in,
                                 __nv_bfloat16* __restrict__ hi,
                                 __nv_bfloat16* __restrict__ lo, int n)
{
    for (int i = blockIdx.x * blockDim.x + threadIdx.x; i < n;
         i += gridDim.x * blockDim.x) {
        float a = in[i];
        __nv_bfloat16 h = __float2bfloat16(a);
        hi[i] = h;
        lo[i] = __float2bfloat16(a - __bfloat162float(h));
    }
}

// ---------------------------------------------------------------------------
// MMA / ldmatrix primitives
// ---------------------------------------------------------------------------
__device__ __forceinline__ void mma_bf16(float* d, const unsigned* a, const unsigned* b)
{
    asm volatile(
        "mma.sync.aligned.m16n8k16.row.col.f32.bf16.bf16.f32 "
        "{%0,%1,%2,%3}, {%4,%5,%6,%7}, {%8,%9}, {%0,%1,%2,%3};\n"
        : "+f"(d[0]), "+f"(d[1]), "+f"(d[2]), "+f"(d[3])
        : "r"(a[0]), "r"(a[1]), "r"(a[2]), "r"(a[3]), "r"(b[0]), "r"(b[1]));
}

__device__ __forceinline__ void ldsm_x4(unsigned* r, const void* p)
{
    unsigned addr = (unsigned)__cvta_generic_to_shared(p);
    asm volatile("ldmatrix.sync.aligned.m8n8.x4.shared.b16 {%0,%1,%2,%3}, [%4];\n"
                 : "=r"(r[0]), "=r"(r[1]), "=r"(r[2]), "=r"(r[3]) : "r"(addr));
}

__device__ __forceinline__ void ldsm_x4_t(unsigned* r, const void* p)
{
    unsigned addr = (unsigned)__cvta_generic_to_shared(p);
    asm volatile("ldmatrix.sync.aligned.m8n8.x4.trans.shared.b16 {%0,%1,%2,%3}, [%4];\n"
                 : "=r"(r[0]), "=r"(r[1]), "=r"(r[2]), "=r"(r[3]) : "r"(addr));
}

// ---------------------------------------------------------------------------
// bf16 3-pass (hi/lo split) tensor-core NT GEMM (sync staging, 2 CTAs/SM).
// OUT_SPLIT=0: fp32 C. OUT_SPLIT=1: bf16 hi/lo outputs, accum scaled by oscale.
// Block tile 128x128x32, 8 warps (2m x 4n), warp tile 64x32, mma m16n8k16.
// ---------------------------------------------------------------------------
#define SLD 40

template<int OUT_SPLIT>
__global__ __launch_bounds__(256, 2)
void gemm_bf16x3_kernel(const __nv_bfloat16* __restrict__ Ahi,
                        const __nv_bfloat16* __restrict__ Alo,
                        const __nv_bfloat16* __restrict__ Bhi,
                        const __nv_bfloat16* __restrict__ Blo,
                        float* __restrict__ C,
                        __nv_bfloat16* __restrict__ Chi,
                        __nv_bfloat16* __restrict__ Clo,
                        float oscale, int M, int N, int K)
{
    __shared__ __align__(16) __nv_bfloat16 sAh[128 * SLD];
    __shared__ __align__(16) __nv_bfloat16 sAl[128 * SLD];
    __shared__ __align__(16) __nv_bfloat16 sBh[128 * SLD];
    __shared__ __align__(16) __nv_bfloat16 sBl[128 * SLD];

    const int tid  = threadIdx.x;
    const int wid  = tid >> 5;
    const int lane = tid & 31;
    const int warp_m = wid & 1;
    const int warp_n = wid >> 1;
    const int row0 = blockIdx.y * 128;
    const int col0 = blockIdx.x * 128;

    float acc[4][4][4];
#pragma unroll
    for (int mt = 0; mt < 4; mt++)
#pragma unroll
        for (int nt = 0; nt < 4; nt++)
#pragma unroll
            for (int i = 0; i < 4; i++) acc[mt][nt][i] = 0.f;

    const int j   = lane >> 3;
    const int r   = lane & 7;
    const int a_row  = (j & 1) * 8 + r;
    const int a_kadd = (j >> 1) * 8;
    const int b_row  = (j >> 1) * 8 + r;
    const int b_kadd = (j & 1) * 8;

    for (int k0 = 0; k0 < K; k0 += 32) {
#pragma unroll
        for (int t = 0; t < 2; t++) {
            int c   = tid + t * 256;
            int row = c >> 2;
            int ck  = (c & 3) * 8;
            size_t ga = (size_t)(row0 + row) * K + k0 + ck;
            size_t gb = (size_t)(col0 + row) * K + k0 + ck;
            int d = row * SLD + ck;
            *(uint4*)&sAh[d] = *(const uint4*)&Ahi[ga];
            *(uint4*)&sAl[d] = *(const uint4*)&Alo[ga];
            *(uint4*)&sBh[d] = *(const uint4*)&Bhi[gb];
            *(uint4*)&sBl[d] = *(const uint4*)&Blo[gb];
        }
        __syncthreads();

#pragma unroll
        for (int ks = 0; ks < 2; ks++) {
            const int kk = ks * 16;
            unsigned ah[4][4], al[4][4], bh[4][2], bl[4][2];
#pragma unroll
            for (int mt = 0; mt < 4; mt++) {
                int m = warp_m * 64 + mt * 16 + a_row;
                ldsm_x4(ah[mt], &sAh[m * SLD + kk + a_kadd]);
                ldsm_x4(al[mt], &sAl[m * SLD + kk + a_kadd]);
            }
#pragma unroll
            for (int p = 0; p < 2; p++) {
                int n = warp_n * 32 + p * 16 + b_row;
                unsigned tmp[4];
                ldsm_x4(tmp, &sBh[n * SLD + kk + b_kadd]);
                bh[p*2][0] = tmp[0]; bh[p*2][1] = tmp[1];
                bh[p*2+1][0] = tmp[2]; bh[p*2+1][1] = tmp[3];
                ldsm_x4(tmp, &sBl[n * SLD + kk + b_kadd]);
                bl[p*2][0] = tmp[0]; bl[p*2][1] = tmp[1];
                bl[p*2+1][0] = tmp[2]; bl[p*2+1][1] = tmp[3];
            }
#pragma unroll
            for (int mt = 0; mt < 4; mt++)
#pragma unroll
                for (int nt = 0; nt < 4; nt++) {
                    mma_bf16(acc[mt][nt], ah[mt], bh[nt]);
                    mma_bf16(acc[mt][nt], ah[mt], bl[nt]);
                    mma_bf16(acc[mt][nt], al[mt], bh[nt]);
                }
        }
        __syncthreads();
    }

    const int g  = lane >> 2;
    const int tt = lane & 3;
#pragma unroll
    for (int mt = 0; mt < 4; mt++) {
        int m = row0 + warp_m * 64 + mt * 16 + g;
#pragma unroll
        for (int nt = 0; nt < 4; nt++) {
            int n = col0 + warp_n * 32 + nt * 8 + 2 * tt;
            if (OUT_SPLIT == 0) {
                *(float2*)&C[(size_t)m * N + n] =
                    make_float2(acc[mt][nt][0], acc[mt][nt][1]);
                *(float2*)&C[(size_t)(m + 8) * N + n] =
                    make_float2(acc[mt][nt][2], acc[mt][nt][3]);
            } else {
#pragma unroll
                for (int rh = 0; rh < 2; rh++) {
                    float v0 = acc[mt][nt][rh*2]   * oscale;
                    float v1 = acc[mt][nt][rh*2+1] * oscale;
                    __nv_bfloat162 h2 = __floats2bfloat162_rn(v0, v1);
                    __nv_bfloat162 l2 = __floats2bfloat162_rn(
                        v0 - __bfloat162float(h2.x), v1 - __bfloat162float(h2.y));
                    size_t idx = (size_t)(m + rh*8) * N + n;
                    *(__nv_bfloat162*)&Chi[idx] = h2;
                    *(__nv_bfloat162*)&Clo[idx] = l2;
                }
            }
        }
    }
}

// ---------------------------------------------------------------------------
// Tensor-core causal flash attention (bf16 hi/lo split, fp32 accum).
// BQ=128 (8 warps x 16 rows), BKV=64, D=64. Q pre-scaled by 1/8 at GEMM.
// S = Qh*Kh + Qh*Kl + Ql*Kh ; PV = Ph*Vh + Ph*Vl + Pl*Vh.
// smem: XOR-swizzled 16B granules (cg ^ (row&7)), rows of 64 bf16.
// NOW 2 CTAs/SM (reg cap 128) for cross-CTA latency hiding.
// ---------------------------------------------------------------------------
#define AQ  128
#define AKV 64

__global__ __launch_bounds__(256, 2)
void flash_attn_mma(const __nv_bfloat16* __restrict__ qhi, const __nv_bfloat16* __restrict__ qlo,
                    const __nv_bfloat16* __restrict__ khi, const __nv_bfloat16* __restrict__ klo,
                    const __nv_bfloat16* __restrict__ vhi, const __nv_bfloat16* __restrict__ vlo,
                    __nv_bfloat16* __restrict__ yhi, __nv_bfloat16* __restrict__ ylo)
{
    extern __shared__ __nv_bfloat16 smem[];
    __nv_bfloat16* sQh = smem;                 // 128*64
    __nv_bfloat16* sQl = sQh + AQ * 64;
    __nv_bfloat16* sKh = sQl + AQ * 64;        // 64*64
    __nv_bfloat16* sKl = sKh + AKV * 64;
    __nv_bfloat16* sVh = sKl + AKV * 64;
    __nv_bfloat16* sVl = sVh + AKV * 64;

    const int tid  = threadIdx.x;
    const int wid  = tid >> 5;
    const int lane = tid & 31;
    const int g    = lane >> 2;
    const int tt   = lane & 3;
    const int mat  = lane >> 3;     // ldmatrix operand index 0..3
    const int mr   = lane & 7;      // row within 8x8 matrix
    const int bh = blockIdx.y;
    const int b  = bh >> 4;
    const int h  = bh & 15;
    const int q0 = blockIdx.x * AQ;

    // Stage Q tile once
    const size_t qbase = ((size_t)(b * T_SEQ + q0)) * CDIM + h * DHEAD;
    for (int i = tid; i < AQ * 8; i += 256) {
        int rr = i >> 3, cg = i & 7;
        int sa = rr * 64 + ((cg ^ (rr & 7)) << 3);
        size_t ga = qbase + (size_t)rr * CDIM + cg * 8;
        *(uint4*)&sQh[sa] = *(const uint4*)&qhi[ga];
        *(uint4*)&sQl[sa] = *(const uint4*)&qlo[ga];
    }
    __syncthreads();

    float o[8][4];
#pragma unroll
    for (int dt = 0; dt < 8; dt++)
#pragma unroll
        for (int i = 0; i < 4; i++) o[dt][i] = 0.f;
    float m0 = -INFINITY, m1 = -INFINITY;
    float l0 = 0.f, l1 = 0.f;

    const int jend = q0 + AQ;
    for (int j0 = 0; j0 < jend; j0 += AKV) {
        // Stage K,V tiles
        const size_t kvbase = ((size_t)(b * T_SEQ + j0)) * CDIM + h * DHEAD;
        for (int i = tid; i < AKV * 8; i += 256) {
            int rr = i >> 3, cg = i & 7;
            int sa = rr * 64 + ((cg ^ (rr & 7)) << 3);
            size_t ga = kvbase + (size_t)rr * CDIM + cg * 8;
            *(uint4*)&sKh[sa] = *(const uint4*)&khi[ga];
            *(uint4*)&sKl[sa] = *(const uint4*)&klo[ga];
            *(uint4*)&sVh[sa] = *(const uint4*)&vhi[ga];
            *(uint4*)&sVl[sa] = *(const uint4*)&vlo[ga];
        }
        __syncthreads();

        // ---- S = Q K^T (3 split passes) ----
        float s[8][4];
#pragma unroll
        for (int nt = 0; nt < 8; nt++)
#pragma unroll
            for (int i = 0; i < 4; i++) s[nt][i] = 0.f;

#pragma unroll
        for (int kc = 0; kc < 4; kc++) {
            unsigned qa_h[4], qa_l[4];
            {
                int row = wid * 16 + (mat & 1) * 8 + mr;
                int cg  = kc * 2 + (mat >> 1);
                int sa  = row * 64 + ((cg ^ (row & 7)) << 3);
                ldsm_x4(qa_h, &sQh[sa]);
                ldsm_x4(qa_l, &sQl[sa]);
            }
#pragma unroll
            for (int jp = 0; jp < 4; jp++) {
                unsigned kb_h[4], kb_l[4];
                int row = jp * 16 + (mat >> 1) * 8 + mr;
                int cg  = kc * 2 + (mat & 1);
                int sa  = row * 64 + ((cg ^ (row & 7)) << 3);
                ldsm_x4(kb_h, &sKh[sa]);
                ldsm_x4(kb_l, &sKl[sa]);
                mma_bf16(s[jp*2],   qa_h, kb_h);
                mma_bf16(s[jp*2],   qa_h, kb_l);
                mma_bf16(s[jp*2],   qa_l, kb_h);
                mma_bf16(s[jp*2+1], qa_h, kb_h + 2);
                mma_bf16(s[jp*2+1], qa_h, kb_l + 2);
                mma_bf16(s[jp*2+1], qa_l, kb_h + 2);
            }
        }

        // ---- causal mask ----
        if (j0 + AKV - 1 > q0 + wid * 16) {
            int row_g  = q0 + wid * 16 + g;
#pragma unroll
            for (int nt = 0; nt < 8; nt++) {
                int col = j0 + nt * 8 + tt * 2;
                if (col     > row_g)     s[nt][0] = -INFINITY;
                if (col + 1 > row_g)     s[nt][1] = -INFINITY;
                if (col     > row_g + 8) s[nt][2] = -INFINITY;
                if (col + 1 > row_g + 8) s[nt][3] = -INFINITY;
            }
        }

        // ---- online softmax ----
        float mx0 = -INFINITY, mx1 = -INFINITY;
#pragma unroll
        for (int nt = 0; nt < 8; nt++) {
            mx0 = fmaxf(mx0, fmaxf(s[nt][0], s[nt][1]));
            mx1 = fmaxf(mx1, fmaxf(s[nt][2], s[nt][3]));
        }
        mx0 = fmaxf(mx0, __shfl_xor_sync(0xffffffffu, mx0, 1));
        mx0 = fmaxf(mx0, __shfl_xor_sync(0xffffffffu, mx0, 2));
        mx1 = fmaxf(mx1, __shfl_xor_sync(0xffffffffu, mx1, 1));
        mx1 = fmaxf(mx1, __shfl_xor_sync(0xffffffffu, mx1, 2));
        float mn0 = fmaxf(m0, mx0), mn1 = fmaxf(m1, mx1);
        float c0 = __expf(m0 - mn0), c1 = __expf(m1 - mn1);
        m0 = mn0; m1 = mn1;
        l0 *= c0;  l1 *= c1;
#pragma unroll
        for (int dt = 0; dt < 8; dt++) {
            o[dt][0] *= c0; o[dt][1] *= c0;
            o[dt][2] *= c1; o[dt][3] *= c1;
        }

        unsigned pH[2][8], pL[2][8];
#pragma unroll
        for (int nt = 0; nt < 8; nt++) {
            float p00 = __expf(s[nt][0] - m0);
            float p01 = __expf(s[nt][1] - m0);
            float p10 = __expf(s[nt][2] - m1);
            float p11 = __expf(s[nt][3] - m1);
            l0 += p00 + p01;
            l1 += p10 + p11;
            __nv_bfloat162 h0 = __floats2bfloat162_rn(p00, p01);
            __nv_bfloat162 h1 = __floats2bfloat162_rn(p10, p11);
            __nv_bfloat162 e0 = __floats2bfloat162_rn(
                p00 - __bfloat162float(h0.x), p01 - __bfloat162float(h0.y));
            __nv_bfloat162 e1 = __floats2bfloat162_rn(
                p10 - __bfloat162float(h1.x), p11 - __bfloat162float(h1.y));
            pH[0][nt] = *reinterpret_cast<unsigned*>(&h0);
            pH[1][nt] = *reinterpret_cast<unsigned*>(&h1);
            pL[0][nt] = *reinterpret_cast<unsigned*>(&e0);
            pL[1][nt] = *reinterpret_cast<unsigned*>(&e1);
        }

        // ---- O += P V (3 split passes) ----
#pragma unroll
        for (int kc = 0; kc < 4; kc++) {
            unsigned pa_h[4] = {pH[0][2*kc], pH[1][2*kc], pH[0][2*kc+1], pH[1][2*kc+1]};
            unsigned pa_l[4] = {pL[0][2*kc], pL[1][2*kc], pL[0][2*kc+1], pL[1][2*kc+1]};
#pragma unroll
            for (int dtp = 0; dtp < 4; dtp++) {
                unsigned vb_h[4], vb_l[4];
                int row = kc * 16 + (mat & 1) * 8 + mr;
                int cg  = dtp * 2 + (mat >> 1);
                int sa  = row * 64 + ((cg ^ (row & 7)) << 3);
                ldsm_x4_t(vb_h, &sVh[sa]);
                ldsm_x4_t(vb_l, &sVl[sa]);
                mma_bf16(o[dtp*2],   pa_h, vb_h);
                mma_bf16(o[dtp*2],   pa_h, vb_l);
                mma_bf16(o[dtp*2],   pa_l, vb_h);
                mma_bf16(o[dtp*2+1], pa_h, vb_h + 2);
                mma_bf16(o[dtp*2+1], pa_h, vb_l + 2);
                mma_bf16(o[dtp*2+1], pa_l, vb_h + 2);
            }
        }
        __syncthreads();
    }

    // ---- epilogue: normalize, split to bf16 hi/lo ----
    l0 += __shfl_xor_sync(0xffffffffu, l0, 1);
    l0 += __shfl_xor_sync(0xffffffffu, l0, 2);
    l1 += __shfl_xor_sync(0xffffffffu, l1, 1);
    l1 += __shfl_xor_sync(0xffffffffu, l1, 2);
    float inv0 = 1.f / l0, inv1 = 1.f / l1;

    size_t orow0 = ((size_t)(b * T_SEQ + q0 + wid * 16 + g)) * CDIM + h * DHEAD;
    size_t orow1 = orow0 + (size_t)8 * CDIM;
#pragma unroll
    for (int dt = 0; dt < 8; dt++) {
        int col = dt * 8 + tt * 2;
        float v0 = o[dt][0] * inv0, v1 = o[dt][1] * inv0;
        __nv_bfloat162 h2 = __floats2bfloat162_rn(v0, v1);
        __nv_bfloat162 l2 = __floats2bfloat162_rn(
            v0 - __bfloat162float(h2.x), v1 - __bfloat162float(h2.y));
        *(__nv_bfloat162*)&yhi[orow0 + col] = h2;
        *(__nv_bfloat162*)&ylo[orow0 + col] = l2;

        float w0 = o[dt][2] * inv1, w1 = o[dt][3] * inv1;
        __nv_bfloat162 h3 = __floats2bfloat162_rn(w0, w1);
        __nv_bfloat162 l3 = __floats2bfloat162_rn(
            w0 - __bfloat162float(h3.x), w1 - __bfloat162float(h3.y));
        *(__nv_bfloat162*)&yhi[orow1 + col] = h3;
        *(__nv_bfloat162*)&ylo[orow1 + col] = l3;
    }
}

// ---------------------------------------------------------------------------
extern "C" void kernel_launch(void* const* d_in, const int* in_sizes, int n_in,
                              void* d_out, int out_size)
{
    const float* x  = (const float*)d_in[0];
    const float* Wq = (const float*)d_in[1];
    const float* Wk = (const float*)d_in[2];
    const float* Wv = (const float*)d_in[3];
    const float* Wp = (const float*)d_in[4];
    float* out = (float*)d_out;

    __nv_bfloat16 *ahi, *alo, *whi, *wlo;
    __nv_bfloat16 *qhi, *qlo, *khi, *klo, *vhi, *vlo;
    cudaGetSymbolAddress((void**)&ahi, g_ahi);
    cudaGetSymbolAddress((void**)&alo, g_alo);
    cudaGetSymbolAddress((void**)&whi, g_whi);
    cudaGetSymbolAddress((void**)&wlo, g_wlo);
    cudaGetSymbolAddress((void**)&qhi, g_qhi);
    cudaGetSymbolAddress((void**)&qlo, g_qlo);
    cudaGetSymbolAddress((void**)&khi, g_khi);
    cudaGetSymbolAddress((void**)&klo, g_klo);
    cudaGetSymbolAddress((void**)&vhi, g_vhi);
    cudaGetSymbolAddress((void**)&vlo, g_vlo);

    static const size_t ATTN_SMEM = (size_t)(AQ * 64 * 2 + AKV * 64 * 4) * sizeof(__nv_bfloat16); // 64KB
    cudaFuncSetAttribute(flash_attn_mma, cudaFuncAttributeMaxDynamicSharedMemorySize, (int)ATTN_SMEM);

    const size_t WSZ = (size_t)CDIM * CDIM;
    const int NX = MROWS * CDIM;

    // Split conversions (input + weights only; y split is fused into attention)
    cvt_split_kernel<<<1024, 256>>>(x,  ahi, alo, NX);
    cvt_split_kernel<<<512, 256>>>(Wq, whi + 0*WSZ, wlo + 0*WSZ, (int)WSZ);
    cvt_split_kernel<<<512, 256>>>(Wk, whi + 1*WSZ, wlo + 1*WSZ, (int)WSZ);
    cvt_split_kernel<<<512, 256>>>(Wv, whi + 2*WSZ, wlo + 2*WSZ, (int)WSZ);
    cvt_split_kernel<<<512, 256>>>(Wp, whi + 3*WSZ, wlo + 3*WSZ, (int)WSZ);

    dim3 ggrid(CDIM / 128, MROWS / 128);   // (8, 64)
    // QKV projections -> bf16 hi/lo (q pre-scaled by 1/sqrt(D) = 0.125)
    gemm_bf16x3_kernel<1><<<ggrid, 256>>>(ahi, alo, whi + 0*WSZ, wlo + 0*WSZ,
                                          nullptr, qhi, qlo, 0.125f, MROWS, CDIM, CDIM);
    gemm_bf16x3_kernel<1><<<ggrid, 256>>>(ahi, alo, whi + 1*WSZ, wlo + 1*WSZ,
                                          nullptr, khi, klo, 1.0f, MROWS, CDIM, CDIM);
    gemm_bf16x3_kernel<1><<<ggrid, 256>>>(ahi, alo, whi + 2*WSZ, wlo + 2*WSZ,
                                          nullptr, vhi, vlo, 1.0f, MROWS, CDIM, CDIM);

    // Attention writes y hi/lo straight into the activation split buffers
    dim3 agrid(T_SEQ / AQ, BATCH * NHEAD);  // (16, 64)
    flash_attn_mma<<<agrid, 256, ATTN_SMEM>>>(qhi, qlo, khi, klo, vhi, vlo, ahi, alo);

    // Output projection -> fp32 out
    gemm_bf16x3_kernel<0><<<ggrid, 256>>>(ahi, alo, whi + 3*WSZ, wlo + 3*WSZ,
                                          out, nullptr, nullptr, 1.0f, MROWS, CDIM, CDIM);
}